// round 4
// baseline (speedup 1.0000x reference)
#include <cuda_runtime.h>
#include <cstddef>

#define S 512
#define NREF 514

// Scratch (allocations are forbidden; device globals are the sanctioned path)
__device__ float g_inv[NREF];
__device__ float g_QL[S * S];
__device__ float g_QRt[S * S];
__device__ float g_Q[S * S];

// ---------------------------------------------------------------------------
// Kernel 1: inv[k] = 2 / (v_k . v_k + 1e-16)   (one warp per reflector)
// ---------------------------------------------------------------------------
__global__ void norms_kernel(const float* __restrict__ V) {
    int w    = (blockIdx.x * blockDim.x + threadIdx.x) >> 5;
    int lane = threadIdx.x & 31;
    if (w >= NREF) return;
    const float4* vp = reinterpret_cast<const float4*>(V + (size_t)w * S) + lane;
    float s = 0.f;
#pragma unroll
    for (int r = 0; r < 4; ++r) {
        float4 t = vp[r * 32];
        s += t.x * t.x + t.y * t.y + t.z * t.z + t.w * t.w;
    }
#pragma unroll
    for (int off = 16; off; off >>= 1) s += __shfl_xor_sync(0xffffffffu, s, off);
    if (lane == 0) g_inv[w] = 2.0f / (s + 1e-16f);
}

// ---------------------------------------------------------------------------
// Kernel 2: build rows of QL = M0..M256 (warps 0..511) and
//           rows of QR^T = M513..M257 (warps 512..1023), one warp per row.
// Row chain: q <- q - inv[k] * (q . v_k) * v_k   (Householder is symmetric)
// ---------------------------------------------------------------------------
__global__ __launch_bounds__(256) void build_kernel(const float* __restrict__ V) {
    int gw   = (blockIdx.x * blockDim.x + threadIdx.x) >> 5;  // 0..1023
    int lane = threadIdx.x & 31;
    int half = gw >> 9;                 // 0 -> QL, 1 -> QR^T
    int row  = gw & 511;
    float* out = half ? g_QRt : g_QL;
    int k     = half ? (NREF - 1) : 0;
    int kstep = half ? -1 : 1;
    const int kcount = 257;

    float q[16];
    int base = lane * 16;
#pragma unroll
    for (int j = 0; j < 16; ++j) q[j] = (base + j == row) ? 1.0f : 0.0f;

    const float4* Vb = reinterpret_cast<const float4*>(V);  // row k -> float4s [k*128, k*128+128)
    int vi = k * 128 + lane * 4;
    float4 c0 = Vb[vi + 0], c1 = Vb[vi + 1], c2 = Vb[vi + 2], c3 = Vb[vi + 3];
    float invk = g_inv[k];

    for (int it = 0; it < kcount; ++it) {
        int kn = k + kstep;
        float4 n0 = c0, n1 = c1, n2 = c2, n3 = c3;
        float invn = invk;
        if (it + 1 < kcount) {  // software prefetch of next reflector (L2 resident)
            int vn = kn * 128 + lane * 4;
            n0 = Vb[vn + 0]; n1 = Vb[vn + 1]; n2 = Vb[vn + 2]; n3 = Vb[vn + 3];
            invn = g_inv[kn];
        }
        // dot(q, v_k), 4 independent accumulator chains
        float d0 = q[0]  * c0.x + q[1]  * c0.y + q[2]  * c0.z + q[3]  * c0.w;
        float d1 = q[4]  * c1.x + q[5]  * c1.y + q[6]  * c1.z + q[7]  * c1.w;
        float d2 = q[8]  * c2.x + q[9]  * c2.y + q[10] * c2.z + q[11] * c2.w;
        float d3 = q[12] * c3.x + q[13] * c3.y + q[14] * c3.z + q[15] * c3.w;
        float d  = (d0 + d1) + (d2 + d3);
#pragma unroll
        for (int off = 16; off; off >>= 1) d += __shfl_xor_sync(0xffffffffu, d, off);
        float sc = d * invk;
        q[0]  -= sc * c0.x; q[1]  -= sc * c0.y; q[2]  -= sc * c0.z; q[3]  -= sc * c0.w;
        q[4]  -= sc * c1.x; q[5]  -= sc * c1.y; q[6]  -= sc * c1.z; q[7]  -= sc * c1.w;
        q[8]  -= sc * c2.x; q[9]  -= sc * c2.y; q[10] -= sc * c2.z; q[11] -= sc * c2.w;
        q[12] -= sc * c3.x; q[13] -= sc * c3.y; q[14] -= sc * c3.z; q[15] -= sc * c3.w;
        c0 = n0; c1 = n1; c2 = n2; c3 = n3; invk = invn; k = kn;
    }

    float4* o = reinterpret_cast<float4*>(out + (size_t)row * S + base);
    o[0] = make_float4(q[0],  q[1],  q[2],  q[3]);
    o[1] = make_float4(q[4],  q[5],  q[6],  q[7]);
    o[2] = make_float4(q[8],  q[9],  q[10], q[11]);
    o[3] = make_float4(q[12], q[13], q[14], q[15]);
}

// ---------------------------------------------------------------------------
// GEMM (NT, K = 512 fixed): C[m][n] = sum_k A[m][k] * B[n][k]
// 128x128 CTA tile, 256 threads, 8x8 per thread (split 4+4 to cut LDS conflicts)
// ---------------------------------------------------------------------------
__global__ __launch_bounds__(256) void gemm_nt128(const float* __restrict__ A,
                                                  const float* __restrict__ B,
                                                  float* __restrict__ C) {
    __shared__ __align__(16) float As[32][132];  // [k][m], pad 132 (16B-aligned rows)
    __shared__ __align__(16) float Bs[32][132];  // [k][n]
    const int bm  = blockIdx.x * 128;
    const int bn  = blockIdx.y * 128;
    const int tid = threadIdx.x;
    const int tx  = tid & 15;
    const int ty  = tid >> 4;

    float acc[8][8];
#pragma unroll
    for (int i = 0; i < 8; ++i)
#pragma unroll
        for (int j = 0; j < 8; ++j) acc[i][j] = 0.f;

    for (int k0 = 0; k0 < 512; k0 += 32) {
#pragma unroll
        for (int r = 0; r < 4; ++r) {
            int idx = tid + r * 256;        // 0..1023
            int m   = idx >> 3;             // 0..127
            int kq  = (idx & 7) << 2;       // 0,4,...,28
            float4 av = *reinterpret_cast<const float4*>(A + (size_t)(bm + m) * 512 + k0 + kq);
            As[kq + 0][m] = av.x; As[kq + 1][m] = av.y; As[kq + 2][m] = av.z; As[kq + 3][m] = av.w;
            float4 bv = *reinterpret_cast<const float4*>(B + (size_t)(bn + m) * 512 + k0 + kq);
            Bs[kq + 0][m] = bv.x; Bs[kq + 1][m] = bv.y; Bs[kq + 2][m] = bv.z; Bs[kq + 3][m] = bv.w;
        }
        __syncthreads();
#pragma unroll 4
        for (int k = 0; k < 32; ++k) {
            float4 a0 = *reinterpret_cast<const float4*>(&As[k][ty * 4]);
            float4 a1 = *reinterpret_cast<const float4*>(&As[k][64 + ty * 4]);
            float4 b0 = *reinterpret_cast<const float4*>(&Bs[k][tx * 4]);
            float4 b1 = *reinterpret_cast<const float4*>(&Bs[k][64 + tx * 4]);
            float a[8] = {a0.x, a0.y, a0.z, a0.w, a1.x, a1.y, a1.z, a1.w};
            float b[8] = {b0.x, b0.y, b0.z, b0.w, b1.x, b1.y, b1.z, b1.w};
#pragma unroll
            for (int i = 0; i < 8; ++i)
#pragma unroll
                for (int j = 0; j < 8; ++j) acc[i][j] += a[i] * b[j];
        }
        __syncthreads();
    }

#pragma unroll
    for (int i = 0; i < 8; ++i) {
        int mi = (i < 4) ? (ty * 4 + i) : (64 + ty * 4 + (i - 4));
        float* cp = C + (size_t)(bm + mi) * 512 + bn;
        *reinterpret_cast<float4*>(cp + tx * 4)      = make_float4(acc[i][0], acc[i][1], acc[i][2], acc[i][3]);
        *reinterpret_cast<float4*>(cp + 64 + tx * 4) = make_float4(acc[i][4], acc[i][5], acc[i][6], acc[i][7]);
    }
}

// Small-tile variant for the 512x512 combine (needs >16 CTAs to fill the chip)
__global__ __launch_bounds__(256) void gemm_nt64(const float* __restrict__ A,
                                                 const float* __restrict__ B,
                                                 float* __restrict__ C) {
    __shared__ __align__(16) float As[32][68];
    __shared__ __align__(16) float Bs[32][68];
    const int bm  = blockIdx.x * 64;
    const int bn  = blockIdx.y * 64;
    const int tid = threadIdx.x;
    const int tx  = tid & 15;
    const int ty  = tid >> 4;

    float acc[4][4];
#pragma unroll
    for (int i = 0; i < 4; ++i)
#pragma unroll
        for (int j = 0; j < 4; ++j) acc[i][j] = 0.f;

    for (int k0 = 0; k0 < 512; k0 += 32) {
#pragma unroll
        for (int r = 0; r < 2; ++r) {
            int idx = tid + r * 256;        // 0..511
            int m   = idx >> 3;             // 0..63
            int kq  = (idx & 7) << 2;
            float4 av = *reinterpret_cast<const float4*>(A + (size_t)(bm + m) * 512 + k0 + kq);
            As[kq + 0][m] = av.x; As[kq + 1][m] = av.y; As[kq + 2][m] = av.z; As[kq + 3][m] = av.w;
            float4 bv = *reinterpret_cast<const float4*>(B + (size_t)(bn + m) * 512 + k0 + kq);
            Bs[kq + 0][m] = bv.x; Bs[kq + 1][m] = bv.y; Bs[kq + 2][m] = bv.z; Bs[kq + 3][m] = bv.w;
        }
        __syncthreads();
#pragma unroll 4
        for (int k = 0; k < 32; ++k) {
            float4 a0 = *reinterpret_cast<const float4*>(&As[k][ty * 4]);
            float4 b0 = *reinterpret_cast<const float4*>(&Bs[k][tx * 4]);
            float a[4] = {a0.x, a0.y, a0.z, a0.w};
            float b[4] = {b0.x, b0.y, b0.z, b0.w};
#pragma unroll
            for (int i = 0; i < 4; ++i)
#pragma unroll
                for (int j = 0; j < 4; ++j) acc[i][j] += a[i] * b[j];
        }
        __syncthreads();
    }

#pragma unroll
    for (int i = 0; i < 4; ++i) {
        float* cp = C + (size_t)(bm + ty * 4 + i) * 512 + bn;
        *reinterpret_cast<float4*>(cp + tx * 4) = make_float4(acc[i][0], acc[i][1], acc[i][2], acc[i][3]);
    }
}

// ---------------------------------------------------------------------------
extern "C" void kernel_launch(void* const* d_in, const int* in_sizes, int n_in,
                              void* d_out, int out_size) {
    const float* x = (const float*)d_in[0];
    const float* V = (const float*)d_in[1];
    if (in_sizes[0] == NREF * S) {  // defensive: detect input ordering by size
        x = (const float*)d_in[1];
        V = (const float*)d_in[0];
    }
    float* y = (float*)d_out;

    float *pQL, *pQRt, *pQ;
    cudaGetSymbolAddress((void**)&pQL, g_QL);
    cudaGetSymbolAddress((void**)&pQRt, g_QRt);
    cudaGetSymbolAddress((void**)&pQ, g_Q);

    norms_kernel<<<129, 128>>>(V);                 // 516 warps, guard >= 514
    build_kernel<<<128, 256>>>(V);                 // 1024 warps: QL rows + QR^T rows
    gemm_nt64<<<dim3(8, 8), 256>>>(pQL, pQRt, pQ); // Q = QL * (QR^T)^T   (512x512x512)
    gemm_nt128<<<dim3(512, 4), 256>>>(x, pQ, y);   // y = x * Q^T         (65536x512x512)
}

// round 6
// speedup vs baseline: 1.0017x; 1.0017x over previous
#include <cuda_runtime.h>
#include <cstddef>

#define S 512
#define NREF 514

// Scratch (allocations are forbidden; device globals are the sanctioned path)
__device__ float g_inv[NREF];
__device__ float g_QL[S * S];
__device__ float g_QRt[S * S];
__device__ float g_Q[S * S];

// ---------------------------------------------------------------------------
// Kernel 1: inv[k] = 2 / (v_k . v_k + 1e-16)   (one warp per reflector)
// ---------------------------------------------------------------------------
__global__ void norms_kernel(const float* __restrict__ V) {
    int w    = (blockIdx.x * blockDim.x + threadIdx.x) >> 5;
    int lane = threadIdx.x & 31;
    if (w >= NREF) return;
    const float4* vp = reinterpret_cast<const float4*>(V + (size_t)w * S) + lane;
    float s = 0.f;
#pragma unroll
    for (int r = 0; r < 4; ++r) {
        float4 t = vp[r * 32];
        s += t.x * t.x + t.y * t.y + t.z * t.z + t.w * t.w;
    }
#pragma unroll
    for (int off = 16; off; off >>= 1) s += __shfl_xor_sync(0xffffffffu, s, off);
    if (lane == 0) g_inv[w] = 2.0f / (s + 1e-16f);
}

// ---------------------------------------------------------------------------
// Kernel 2: build rows of QL = M0..M256 (warps 0..511) and
//           rows of QR^T = M513..M257 (warps 512..1023), one warp per row.
// Row chain: q <- q - inv[k] * (q . v_k) * v_k   (Householder is symmetric)
// ---------------------------------------------------------------------------
__global__ __launch_bounds__(256) void build_kernel(const float* __restrict__ V) {
    int gw   = (blockIdx.x * blockDim.x + threadIdx.x) >> 5;  // 0..1023
    int lane = threadIdx.x & 31;
    int half = gw >> 9;                 // 0 -> QL, 1 -> QR^T
    int row  = gw & 511;
    float* out = half ? g_QRt : g_QL;
    int k     = half ? (NREF - 1) : 0;
    int kstep = half ? -1 : 1;
    const int kcount = 257;

    float q[16];
    int base = lane * 16;
#pragma unroll
    for (int j = 0; j < 16; ++j) q[j] = (base + j == row) ? 1.0f : 0.0f;

    const float4* Vb = reinterpret_cast<const float4*>(V);  // row k -> float4s [k*128, k*128+128)
    int vi = k * 128 + lane * 4;
    float4 c0 = Vb[vi + 0], c1 = Vb[vi + 1], c2 = Vb[vi + 2], c3 = Vb[vi + 3];
    float invk = g_inv[k];

    for (int it = 0; it < kcount; ++it) {
        int kn = k + kstep;
        float4 n0 = c0, n1 = c1, n2 = c2, n3 = c3;
        float invn = invk;
        if (it + 1 < kcount) {  // software prefetch of next reflector (L2 resident)
            int vn = kn * 128 + lane * 4;
            n0 = Vb[vn + 0]; n1 = Vb[vn + 1]; n2 = Vb[vn + 2]; n3 = Vb[vn + 3];
            invn = g_inv[kn];
        }
        // dot(q, v_k), 4 independent accumulator chains
        float d0 = q[0]  * c0.x + q[1]  * c0.y + q[2]  * c0.z + q[3]  * c0.w;
        float d1 = q[4]  * c1.x + q[5]  * c1.y + q[6]  * c1.z + q[7]  * c1.w;
        float d2 = q[8]  * c2.x + q[9]  * c2.y + q[10] * c2.z + q[11] * c2.w;
        float d3 = q[12] * c3.x + q[13] * c3.y + q[14] * c3.z + q[15] * c3.w;
        float d  = (d0 + d1) + (d2 + d3);
#pragma unroll
        for (int off = 16; off; off >>= 1) d += __shfl_xor_sync(0xffffffffu, d, off);
        float sc = d * invk;
        q[0]  -= sc * c0.x; q[1]  -= sc * c0.y; q[2]  -= sc * c0.z; q[3]  -= sc * c0.w;
        q[4]  -= sc * c1.x; q[5]  -= sc * c1.y; q[6]  -= sc * c1.z; q[7]  -= sc * c1.w;
        q[8]  -= sc * c2.x; q[9]  -= sc * c2.y; q[10] -= sc * c2.z; q[11] -= sc * c2.w;
        q[12] -= sc * c3.x; q[13] -= sc * c3.y; q[14] -= sc * c3.z; q[15] -= sc * c3.w;
        c0 = n0; c1 = n1; c2 = n2; c3 = n3; invk = invn; k = kn;
    }

    float4* o = reinterpret_cast<float4*>(out + (size_t)row * S + base);
    o[0] = make_float4(q[0],  q[1],  q[2],  q[3]);
    o[1] = make_float4(q[4],  q[5],  q[6],  q[7]);
    o[2] = make_float4(q[8],  q[9],  q[10], q[11]);
    o[3] = make_float4(q[12], q[13], q[14], q[15]);
}

// ---------------------------------------------------------------------------
// GEMM (NT, K = 512 fixed): C[m][n] = sum_k A[m][k] * B[n][k]
// 128x128 CTA tile, 256 threads, 8x8 per thread (split 4+4 to cut LDS conflicts)
// ---------------------------------------------------------------------------
__global__ __launch_bounds__(256) void gemm_nt128(const float* __restrict__ A,
                                                  const float* __restrict__ B,
                                                  float* __restrict__ C) {
    __shared__ __align__(16) float As[32][132];  // [k][m], pad 132 (16B-aligned rows)
    __shared__ __align__(16) float Bs[32][132];  // [k][n]
    const int bm  = blockIdx.x * 128;
    const int bn  = blockIdx.y * 128;
    const int tid = threadIdx.x;
    const int tx  = tid & 15;
    const int ty  = tid >> 4;

    float acc[8][8];
#pragma unroll
    for (int i = 0; i < 8; ++i)
#pragma unroll
        for (int j = 0; j < 8; ++j) acc[i][j] = 0.f;

    for (int k0 = 0; k0 < 512; k0 += 32) {
#pragma unroll
        for (int r = 0; r < 4; ++r) {
            int idx = tid + r * 256;        // 0..1023
            int m   = idx >> 3;             // 0..127
            int kq  = (idx & 7) << 2;       // 0,4,...,28
            float4 av = *reinterpret_cast<const float4*>(A + (size_t)(bm + m) * 512 + k0 + kq);
            As[kq + 0][m] = av.x; As[kq + 1][m] = av.y; As[kq + 2][m] = av.z; As[kq + 3][m] = av.w;
            float4 bv = *reinterpret_cast<const float4*>(B + (size_t)(bn + m) * 512 + k0 + kq);
            Bs[kq + 0][m] = bv.x; Bs[kq + 1][m] = bv.y; Bs[kq + 2][m] = bv.z; Bs[kq + 3][m] = bv.w;
        }
        __syncthreads();
#pragma unroll 4
        for (int k = 0; k < 32; ++k) {
            float4 a0 = *reinterpret_cast<const float4*>(&As[k][ty * 4]);
            float4 a1 = *reinterpret_cast<const float4*>(&As[k][64 + ty * 4]);
            float4 b0 = *reinterpret_cast<const float4*>(&Bs[k][tx * 4]);
            float4 b1 = *reinterpret_cast<const float4*>(&Bs[k][64 + tx * 4]);
            float a[8] = {a0.x, a0.y, a0.z, a0.w, a1.x, a1.y, a1.z, a1.w};
            float b[8] = {b0.x, b0.y, b0.z, b0.w, b1.x, b1.y, b1.z, b1.w};
#pragma unroll
            for (int i = 0; i < 8; ++i)
#pragma unroll
                for (int j = 0; j < 8; ++j) acc[i][j] += a[i] * b[j];
        }
        __syncthreads();
    }

#pragma unroll
    for (int i = 0; i < 8; ++i) {
        int mi = (i < 4) ? (ty * 4 + i) : (64 + ty * 4 + (i - 4));
        float* cp = C + (size_t)(bm + mi) * 512 + bn;
        *reinterpret_cast<float4*>(cp + tx * 4)      = make_float4(acc[i][0], acc[i][1], acc[i][2], acc[i][3]);
        *reinterpret_cast<float4*>(cp + 64 + tx * 4) = make_float4(acc[i][4], acc[i][5], acc[i][6], acc[i][7]);
    }
}

// Small-tile variant for the 512x512 combine (needs >16 CTAs to fill the chip)
__global__ __launch_bounds__(256) void gemm_nt64(const float* __restrict__ A,
                                                 const float* __restrict__ B,
                                                 float* __restrict__ C) {
    __shared__ __align__(16) float As[32][68];
    __shared__ __align__(16) float Bs[32][68];
    const int bm  = blockIdx.x * 64;
    const int bn  = blockIdx.y * 64;
    const int tid = threadIdx.x;
    const int tx  = tid & 15;
    const int ty  = tid >> 4;

    float acc[4][4];
#pragma unroll
    for (int i = 0; i < 4; ++i)
#pragma unroll
        for (int j = 0; j < 4; ++j) acc[i][j] = 0.f;

    for (int k0 = 0; k0 < 512; k0 += 32) {
#pragma unroll
        for (int r = 0; r < 2; ++r) {
            int idx = tid + r * 256;        // 0..511
            int m   = idx >> 3;             // 0..63
            int kq  = (idx & 7) << 2;
            float4 av = *reinterpret_cast<const float4*>(A + (size_t)(bm + m) * 512 + k0 + kq);
            As[kq + 0][m] = av.x; As[kq + 1][m] = av.y; As[kq + 2][m] = av.z; As[kq + 3][m] = av.w;
            float4 bv = *reinterpret_cast<const float4*>(B + (size_t)(bn + m) * 512 + k0 + kq);
            Bs[kq + 0][m] = bv.x; Bs[kq + 1][m] = bv.y; Bs[kq + 2][m] = bv.z; Bs[kq + 3][m] = bv.w;
        }
        __syncthreads();
#pragma unroll 4
        for (int k = 0; k < 32; ++k) {
            float4 a0 = *reinterpret_cast<const float4*>(&As[k][ty * 4]);
            float4 b0 = *reinterpret_cast<const float4*>(&Bs[k][tx * 4]);
            float a[4] = {a0.x, a0.y, a0.z, a0.w};
            float b[4] = {b0.x, b0.y, b0.z, b0.w};
#pragma unroll
            for (int i = 0; i < 4; ++i)
#pragma unroll
                for (int j = 0; j < 4; ++j) acc[i][j] += a[i] * b[j];
        }
        __syncthreads();
    }

#pragma unroll
    for (int i = 0; i < 4; ++i) {
        float* cp = C + (size_t)(bm + ty * 4 + i) * 512 + bn;
        *reinterpret_cast<float4*>(cp + tx * 4) = make_float4(acc[i][0], acc[i][1], acc[i][2], acc[i][3]);
    }
}

// ---------------------------------------------------------------------------
extern "C" void kernel_launch(void* const* d_in, const int* in_sizes, int n_in,
                              void* d_out, int out_size) {
    const float* x = (const float*)d_in[0];
    const float* V = (const float*)d_in[1];
    if (in_sizes[0] == NREF * S) {  // defensive: detect input ordering by size
        x = (const float*)d_in[1];
        V = (const float*)d_in[0];
    }
    float* y = (float*)d_out;

    float *pQL, *pQRt, *pQ;
    cudaGetSymbolAddress((void**)&pQL, g_QL);
    cudaGetSymbolAddress((void**)&pQRt, g_QRt);
    cudaGetSymbolAddress((void**)&pQ, g_Q);

    norms_kernel<<<129, 128>>>(V);                 // 516 warps, guard >= 514
    build_kernel<<<128, 256>>>(V);                 // 1024 warps: QL rows + QR^T rows
    gemm_nt64<<<dim3(8, 8), 256>>>(pQL, pQRt, pQ); // Q = QL * (QR^T)^T   (512x512x512)
    gemm_nt128<<<dim3(512, 4), 256>>>(x, pQ, y);   // y = x * Q^T         (65536x512x512)
}

// round 7
// speedup vs baseline: 1.0156x; 1.0139x over previous
#include <cuda_runtime.h>
#include <cstddef>

#define S 512
#define NREF 514

// Scratch (allocations are forbidden; device globals are the sanctioned path)
__device__ float g_inv[NREF];
__device__ float g_QL[S * S];
__device__ float g_QRt[S * S];
__device__ float g_Q[S * S];

// ---------------------------------------------------------------------------
// Kernel 1: inv[k] = 2 / (v_k . v_k + 1e-16)   (one warp per reflector)
// ---------------------------------------------------------------------------
__global__ void norms_kernel(const float* __restrict__ V) {
    int w    = (blockIdx.x * blockDim.x + threadIdx.x) >> 5;
    int lane = threadIdx.x & 31;
    if (w >= NREF) return;
    const float4* vp = reinterpret_cast<const float4*>(V + (size_t)w * S) + lane;
    float s = 0.f;
#pragma unroll
    for (int r = 0; r < 4; ++r) {
        float4 t = vp[r * 32];
        s += t.x * t.x + t.y * t.y + t.z * t.z + t.w * t.w;
    }
#pragma unroll
    for (int off = 16; off; off >>= 1) s += __shfl_xor_sync(0xffffffffu, s, off);
    if (lane == 0) g_inv[w] = 2.0f / (s + 1e-16f);
}

// ---------------------------------------------------------------------------
// Kernel 2: build rows of QL = M0..M256 (warps 0..511) and
//           rows of QR^T = M513..M257 (warps 512..1023), one warp per row.
// Row chain: q <- q - inv[k] * (q . v_k) * v_k   (Householder is symmetric)
// ---------------------------------------------------------------------------
__global__ __launch_bounds__(256) void build_kernel(const float* __restrict__ V) {
    int gw   = (blockIdx.x * blockDim.x + threadIdx.x) >> 5;  // 0..1023
    int lane = threadIdx.x & 31;
    int half = gw >> 9;                 // 0 -> QL, 1 -> QR^T
    int row  = gw & 511;
    float* out = half ? g_QRt : g_QL;
    int k     = half ? (NREF - 1) : 0;
    int kstep = half ? -1 : 1;
    const int kcount = 257;

    float q[16];
    int base = lane * 16;
#pragma unroll
    for (int j = 0; j < 16; ++j) q[j] = (base + j == row) ? 1.0f : 0.0f;

    const float4* Vb = reinterpret_cast<const float4*>(V);  // row k -> float4s [k*128, k*128+128)
    int vi = k * 128 + lane * 4;
    float4 c0 = Vb[vi + 0], c1 = Vb[vi + 1], c2 = Vb[vi + 2], c3 = Vb[vi + 3];
    float invk = g_inv[k];

    for (int it = 0; it < kcount; ++it) {
        int kn = k + kstep;
        float4 n0 = c0, n1 = c1, n2 = c2, n3 = c3;
        float invn = invk;
        if (it + 1 < kcount) {  // software prefetch of next reflector (L2 resident)
            int vn = kn * 128 + lane * 4;
            n0 = Vb[vn + 0]; n1 = Vb[vn + 1]; n2 = Vb[vn + 2]; n3 = Vb[vn + 3];
            invn = g_inv[kn];
        }
        // dot(q, v_k), 4 independent accumulator chains
        float d0 = q[0]  * c0.x + q[1]  * c0.y + q[2]  * c0.z + q[3]  * c0.w;
        float d1 = q[4]  * c1.x + q[5]  * c1.y + q[6]  * c1.z + q[7]  * c1.w;
        float d2 = q[8]  * c2.x + q[9]  * c2.y + q[10] * c2.z + q[11] * c2.w;
        float d3 = q[12] * c3.x + q[13] * c3.y + q[14] * c3.z + q[15] * c3.w;
        float d  = (d0 + d1) + (d2 + d3);
#pragma unroll
        for (int off = 16; off; off >>= 1) d += __shfl_xor_sync(0xffffffffu, d, off);
        float sc = d * invk;
        q[0]  -= sc * c0.x; q[1]  -= sc * c0.y; q[2]  -= sc * c0.z; q[3]  -= sc * c0.w;
        q[4]  -= sc * c1.x; q[5]  -= sc * c1.y; q[6]  -= sc * c1.z; q[7]  -= sc * c1.w;
        q[8]  -= sc * c2.x; q[9]  -= sc * c2.y; q[10] -= sc * c2.z; q[11] -= sc * c2.w;
        q[12] -= sc * c3.x; q[13] -= sc * c3.y; q[14] -= sc * c3.z; q[15] -= sc * c3.w;
        c0 = n0; c1 = n1; c2 = n2; c3 = n3; invk = invn; k = kn;
    }

    float4* o = reinterpret_cast<float4*>(out + (size_t)row * S + base);
    o[0] = make_float4(q[0],  q[1],  q[2],  q[3]);
    o[1] = make_float4(q[4],  q[5],  q[6],  q[7]);
    o[2] = make_float4(q[8],  q[9],  q[10], q[11]);
    o[3] = make_float4(q[12], q[13], q[14], q[15]);
}

// ---------------------------------------------------------------------------
// GEMM (NT, K = 512 fixed): C[m][n] = sum_k A[m][k] * B[n][k]
// 128x128 CTA tile, 256 threads, 8x8 per thread (split 4+4 to cut LDS conflicts)
// ---------------------------------------------------------------------------
__global__ __launch_bounds__(256) void gemm_nt128(const float* __restrict__ A,
                                                  const float* __restrict__ B,
                                                  float* __restrict__ C) {
    __shared__ __align__(16) float As[32][132];  // [k][m], pad 132 (16B-aligned rows)
    __shared__ __align__(16) float Bs[32][132];  // [k][n]
    const int bm  = blockIdx.x * 128;
    const int bn  = blockIdx.y * 128;
    const int tid = threadIdx.x;
    const int tx  = tid & 15;
    const int ty  = tid >> 4;

    float acc[8][8];
#pragma unroll
    for (int i = 0; i < 8; ++i)
#pragma unroll
        for (int j = 0; j < 8; ++j) acc[i][j] = 0.f;

    for (int k0 = 0; k0 < 512; k0 += 32) {
#pragma unroll
        for (int r = 0; r < 4; ++r) {
            int idx = tid + r * 256;        // 0..1023
            int m   = idx >> 3;             // 0..127
            int kq  = (idx & 7) << 2;       // 0,4,...,28
            float4 av = *reinterpret_cast<const float4*>(A + (size_t)(bm + m) * 512 + k0 + kq);
            As[kq + 0][m] = av.x; As[kq + 1][m] = av.y; As[kq + 2][m] = av.z; As[kq + 3][m] = av.w;
            float4 bv = *reinterpret_cast<const float4*>(B + (size_t)(bn + m) * 512 + k0 + kq);
            Bs[kq + 0][m] = bv.x; Bs[kq + 1][m] = bv.y; Bs[kq + 2][m] = bv.z; Bs[kq + 3][m] = bv.w;
        }
        __syncthreads();
#pragma unroll 4
        for (int k = 0; k < 32; ++k) {
            float4 a0 = *reinterpret_cast<const float4*>(&As[k][ty * 4]);
            float4 a1 = *reinterpret_cast<const float4*>(&As[k][64 + ty * 4]);
            float4 b0 = *reinterpret_cast<const float4*>(&Bs[k][tx * 4]);
            float4 b1 = *reinterpret_cast<const float4*>(&Bs[k][64 + tx * 4]);
            float a[8] = {a0.x, a0.y, a0.z, a0.w, a1.x, a1.y, a1.z, a1.w};
            float b[8] = {b0.x, b0.y, b0.z, b0.w, b1.x, b1.y, b1.z, b1.w};
#pragma unroll
            for (int i = 0; i < 8; ++i)
#pragma unroll
                for (int j = 0; j < 8; ++j) acc[i][j] += a[i] * b[j];
        }
        __syncthreads();
    }

#pragma unroll
    for (int i = 0; i < 8; ++i) {
        int mi = (i < 4) ? (ty * 4 + i) : (64 + ty * 4 + (i - 4));
        float* cp = C + (size_t)(bm + mi) * 512 + bn;
        *reinterpret_cast<float4*>(cp + tx * 4)      = make_float4(acc[i][0], acc[i][1], acc[i][2], acc[i][3]);
        *reinterpret_cast<float4*>(cp + 64 + tx * 4) = make_float4(acc[i][4], acc[i][5], acc[i][6], acc[i][7]);
    }
}

// Small-tile variant for the 512x512 combine (needs >16 CTAs to fill the chip)
__global__ __launch_bounds__(256) void gemm_nt64(const float* __restrict__ A,
                                                 const float* __restrict__ B,
                                                 float* __restrict__ C) {
    __shared__ __align__(16) float As[32][68];
    __shared__ __align__(16) float Bs[32][68];
    const int bm  = blockIdx.x * 64;
    const int bn  = blockIdx.y * 64;
    const int tid = threadIdx.x;
    const int tx  = tid & 15;
    const int ty  = tid >> 4;

    float acc[4][4];
#pragma unroll
    for (int i = 0; i < 4; ++i)
#pragma unroll
        for (int j = 0; j < 4; ++j) acc[i][j] = 0.f;

    for (int k0 = 0; k0 < 512; k0 += 32) {
#pragma unroll
        for (int r = 0; r < 2; ++r) {
            int idx = tid + r * 256;        // 0..511
            int m   = idx >> 3;             // 0..63
            int kq  = (idx & 7) << 2;
            float4 av = *reinterpret_cast<const float4*>(A + (size_t)(bm + m) * 512 + k0 + kq);
            As[kq + 0][m] = av.x; As[kq + 1][m] = av.y; As[kq + 2][m] = av.z; As[kq + 3][m] = av.w;
            float4 bv = *reinterpret_cast<const float4*>(B + (size_t)(bn + m) * 512 + k0 + kq);
            Bs[kq + 0][m] = bv.x; Bs[kq + 1][m] = bv.y; Bs[kq + 2][m] = bv.z; Bs[kq + 3][m] = bv.w;
        }
        __syncthreads();
#pragma unroll 4
        for (int k = 0; k < 32; ++k) {
            float4 a0 = *reinterpret_cast<const float4*>(&As[k][ty * 4]);
            float4 b0 = *reinterpret_cast<const float4*>(&Bs[k][tx * 4]);
            float a[4] = {a0.x, a0.y, a0.z, a0.w};
            float b[4] = {b0.x, b0.y, b0.z, b0.w};
#pragma unroll
            for (int i = 0; i < 4; ++i)
#pragma unroll
                for (int j = 0; j < 4; ++j) acc[i][j] += a[i] * b[j];
        }
        __syncthreads();
    }

#pragma unroll
    for (int i = 0; i < 4; ++i) {
        float* cp = C + (size_t)(bm + ty * 4 + i) * 512 + bn;
        *reinterpret_cast<float4*>(cp + tx * 4) = make_float4(acc[i][0], acc[i][1], acc[i][2], acc[i][3]);
    }
}

// ---------------------------------------------------------------------------
extern "C" void kernel_launch(void* const* d_in, const int* in_sizes, int n_in,
                              void* d_out, int out_size) {
    const float* x = (const float*)d_in[0];
    const float* V = (const float*)d_in[1];
    if (in_sizes[0] == NREF * S) {  // defensive: detect input ordering by size
        x = (const float*)d_in[1];
        V = (const float*)d_in[0];
    }
    float* y = (float*)d_out;

    float *pQL, *pQRt, *pQ;
    cudaGetSymbolAddress((void**)&pQL, g_QL);
    cudaGetSymbolAddress((void**)&pQRt, g_QRt);
    cudaGetSymbolAddress((void**)&pQ, g_Q);

    norms_kernel<<<129, 128>>>(V);                 // 516 warps, guard >= 514
    build_kernel<<<128, 256>>>(V);                 // 1024 warps: QL rows + QR^T rows
    gemm_nt64<<<dim3(8, 8), 256>>>(pQL, pQRt, pQ); // Q = QL * (QR^T)^T   (512x512x512)
    gemm_nt128<<<dim3(512, 4), 256>>>(x, pQ, y);   // y = x * Q^T         (65536x512x512)
}